// round 15
// baseline (speedup 1.0000x reference)
#include <cuda_runtime.h>
#include <cuda.h>        // types/enums only; no link-time driver symbols used
#include <cuda_bf16.h>
#include <cstdint>
#include <dlfcn.h>

// Problem constants: B=32, N=8192, C=512, K=128
#define PB    32
#define PN    8192
#define PC    512
#define PK    128
#define TPB   256
#define WORDS 256                 // bitmask words per batch (PN/32)
#define TOTAL (PB * PN)           // 262144
#define NCTA  (TOTAL / TPB)       // 1024

// Scratch (zero-init at module load; emit kernel restores zeros every launch).
__device__ unsigned int g_mask[PB * WORDS];

// ---------------------------------------------------------------------------
// TMA gather: one TMA command per CTA fetches 256 strided 32B windows (the
// aligned sector containing column `id`) packed into SMEM. Bypasses the SM
// L1tex miss-tracking path entirely.
// ---------------------------------------------------------------------------
__global__ void __launch_bounds__(TPB) tma_gather_kernel(
    const __grid_constant__ CUtensorMap tmap,
    const int*   __restrict__ id_ptr,
    float*       __restrict__ out)
{
    __shared__ __align__(128) float s_tile[TPB * 8];   // 256 rows x 8 floats
    __shared__ __align__(8)  unsigned long long s_mbar;

    const int t   = threadIdx.x;
    const int idx = blockIdx.x * TPB + t;              // global (b,n) flat
    const int id  = __ldg(id_ptr);

    const uint32_t mbar = (uint32_t)__cvta_generic_to_shared(&s_mbar);
    const uint32_t dst  = (uint32_t)__cvta_generic_to_shared(s_tile);

    if (t == 0) {
        asm volatile("mbarrier.init.shared.b64 [%0], %1;" :: "r"(mbar), "r"(1) : "memory");
        asm volatile("fence.proxy.async.shared::cta;" ::: "memory");
    }
    __syncthreads();

    if (t == 0) {
        asm volatile("mbarrier.arrive.expect_tx.shared.b64 _, [%0], %1;"
                     :: "r"(mbar), "r"(TPB * 32) : "memory");
        int cx = id & ~7;                    // aligned 8-float (32B) window
        int cy = blockIdx.x * TPB;           // first row of this CTA's slice
        asm volatile(
            "cp.async.bulk.tensor.2d.shared::cta.global.tile.mbarrier::complete_tx::bytes "
            "[%0], [%1, {%2, %3}], [%4];"
            :: "r"(dst), "l"(&tmap), "r"(cx), "r"(cy), "r"(mbar) : "memory");
    }

    // Wait (parity 0) with acquire so the SMEM reads below are ordered.
    {
        unsigned done;
        asm volatile(
            "{\n .reg .pred p;\n"
            " mbarrier.try_wait.parity.acquire.cta.shared::cta.b64 p, [%1], %2;\n"
            " selp.b32 %0, 1, 0, p;\n}"
            : "=r"(done) : "r"(mbar), "r"(0) : "memory");
        while (!done) {
            asm volatile(
                "{\n .reg .pred p;\n"
                " mbarrier.try_wait.parity.acquire.cta.shared::cta.b64 p, [%1], %2, 0x989680;\n"
                " selp.b32 %0, 1, 0, p;\n}"
                : "=r"(done) : "r"(mbar), "r"(0) : "memory");
        }
    }

    float v = s_tile[t * 8 + (id & 7)];

    // block_id output (coalesced)
    out[idx] = v;

    // stage hit into per-batch bitmask via REDG (no return -> no wait)
    if (v != 0.0f) {
        const int b = idx >> 13;             // idx / PN
        const int n = idx & (PN - 1);
        asm volatile("red.global.or.b32 [%0], %1;"
                     :: "l"(&g_mask[b * WORDS + (n >> 5)]), "r"(1u << (n & 31))
                     : "memory");
    }
}

// ---------------------------------------------------------------------------
// Fallback gather (R14, proven): used only if driver-API resolution fails.
// ---------------------------------------------------------------------------
__global__ void __launch_bounds__(TPB) ldg_gather_kernel(
    const float* __restrict__ one_hot,
    const int*   __restrict__ id_ptr,
    float*       __restrict__ out)
{
    const int idx = blockIdx.x * TPB + threadIdx.x;
    const int id  = __ldg(id_ptr);
    float v = __ldcg(one_hot + (size_t)idx * PC + id);
    out[idx] = v;
    if (v != 0.0f) {
        const int b = idx >> 13;
        const int n = idx & (PN - 1);
        asm volatile("red.global.or.b32 [%0], %1;"
                     :: "l"(&g_mask[b * WORDS + (n >> 5)]), "r"(1u << (n & 31))
                     : "memory");
    }
}

// ---------------------------------------------------------------------------
// Emit kernel (R14, proven): scan bitmask, emit K ascending indices, reset.
// ---------------------------------------------------------------------------
__global__ void __launch_bounds__(TPB) emit_kernel(float* __restrict__ out)
{
    const int b    = blockIdx.x;
    const int t    = threadIdx.x;
    const int lane = t & 31;
    const int wid  = t >> 5;

    unsigned w = __ldcg(&g_mask[b * WORDS + t]);
    int cnt = __popc(w);

    int inc = cnt;
#pragma unroll
    for (int d = 1; d < 32; d <<= 1) {
        int y = __shfl_up_sync(0xffffffffu, inc, d);
        if (lane >= d) inc += y;
    }

    __shared__ int s_wsum[8];
    if (lane == 31) s_wsum[wid] = inc;
    __syncthreads();

    if (wid == 0) {
        int wv = (lane < 8) ? s_wsum[lane] : 0;
        int winc = wv;
#pragma unroll
        for (int d = 1; d < 8; d <<= 1) {
            int y = __shfl_up_sync(0xffffffffu, winc, d);
            if (lane >= d) winc += y;
        }
        if (lane < 8) s_wsum[lane] = winc - wv;
    }
    __syncthreads();

    int pos = s_wsum[wid] + (inc - cnt);

    float* oidx = out + (size_t)PB * PN + (size_t)b * PK;
    while (w) {
        int bit = __ffs(w) - 1;
        w &= w - 1;
        if (pos < PK) oidx[pos] = (float)(t * 32 + bit);
        pos++;
    }

    g_mask[b * WORDS + t] = 0u;   // reset for next graph replay
}

// ---------------------------------------------------------------------------
// Host: build tensormap via dlopen'd driver API (no -lcuda needed).
// ---------------------------------------------------------------------------
typedef CUresult (*EncodeTiledFn)(
    CUtensorMap*, CUtensorMapDataType, cuuint32_t, void*,
    const cuuint64_t*, const cuuint64_t*, const cuuint32_t*, const cuuint32_t*,
    CUtensorMapInterleave, CUtensorMapSwizzle, CUtensorMapL2promotion,
    CUtensorMapFloatOOBfill);

extern "C" void kernel_launch(void* const* d_in, const int* in_sizes, int n_in,
                              void* d_out, int out_size)
{
    const float* one_hot = (const float*)d_in[0];
    const int*   id_ptr  = (const int*)d_in[1];
    float*       out     = (float*)d_out;

    (void)in_sizes; (void)n_in; (void)out_size;

    bool tma_ok = false;
    CUtensorMap tmap;

    void* h = dlopen("libcuda.so.1", RTLD_NOW | RTLD_GLOBAL);
    EncodeTiledFn enc = h ? (EncodeTiledFn)dlsym(h, "cuTensorMapEncodeTiled") : nullptr;
    if (enc) {
        // one_hot viewed as 2D: d0 = 512 floats (row), d1 = 262144 rows
        cuuint64_t dims[2]    = {(cuuint64_t)PC, (cuuint64_t)TOTAL};
        cuuint64_t strides[1] = {(cuuint64_t)PC * sizeof(float)};   // 2048 B
        cuuint32_t box[2]     = {8, TPB};                           // 32B x 256 rows
        cuuint32_t estr[2]    = {1, 1};
        CUresult r = enc(&tmap, CU_TENSOR_MAP_DATA_TYPE_FLOAT32, 2,
                         (void*)one_hot, dims, strides, box, estr,
                         CU_TENSOR_MAP_INTERLEAVE_NONE,
                         CU_TENSOR_MAP_SWIZZLE_NONE,
                         CU_TENSOR_MAP_L2_PROMOTION_NONE,
                         CU_TENSOR_MAP_FLOAT_OOB_FILL_NONE);
        tma_ok = (r == CUDA_SUCCESS);
    }

    if (tma_ok)
        tma_gather_kernel<<<NCTA, TPB>>>(tmap, id_ptr, out);
    else
        ldg_gather_kernel<<<NCTA, TPB>>>(one_hot, id_ptr, out);

    emit_kernel<<<PB, TPB>>>(out);
}

// round 16
// speedup vs baseline: 1.0294x; 1.0294x over previous
#include <cuda_runtime.h>
#include <cuda_bf16.h>
#include <cstdint>

// Problem constants: B=32, N=8192, C=512, K=128
#define PB    32
#define PN    8192
#define PC    512
#define PK    128
#define SEGS  16        // CTAs per batch (each CTA covers 2x256 elements)
#define TPB   256
#define EPT   2         // elements per thread (n, n+4096)
#define HALF  4096      // PN/2
#define WORDS 256       // bitmask words per batch (PN/32)

// Scratch (zero-init at module load; finisher restores zeros every launch).
__device__ unsigned int g_mask[PB * WORDS];
__device__ unsigned int g_done[PB];

__global__ void __launch_bounds__(TPB) fused_filter_kernel(
    const float* __restrict__ one_hot,
    const int*   __restrict__ id_ptr,
    float*       __restrict__ out)
{
    const int g    = blockIdx.x;          // 0 .. PB*SEGS-1 (512)
    const int b    = g >> 4;              // batch
    const int seg  = g & (SEGS - 1);      // segment within batch
    const int t    = threadIdx.x;
    const int lane = t & 31;
    const int wid  = t >> 5;              // 0..7

    const int id = __ldg(id_ptr);
    const int n0 = seg * TPB + t;         // first-half position
    const int n1 = n0 + HALF;             // second-half position
    const size_t base = (size_t)b * PN;

    // ---- two independent scattered L2 loads (MLP=2, front-batched) ----
    const float* src = one_hot + base * PC + id;
    float v0 = __ldcg(src + (size_t)n0 * PC);
    float v1 = __ldcg(src + (size_t)n1 * PC);

    // ---- block_id output (coalesced) ----
    out[base + n0] = v0;
    out[base + n1] = v1;

    // ---- stage hits via REDG bitmask (no return -> no atomic wait) ----
    if (v0 != 0.0f)
        asm volatile("red.global.or.b32 [%0], %1;"
                     :: "l"(&g_mask[b * WORDS + (n0 >> 5)]), "r"(1u << (n0 & 31))
                     : "memory");
    if (v1 != 0.0f)
        asm volatile("red.global.or.b32 [%0], %1;"
                     :: "l"(&g_mask[b * WORDS + (n1 >> 5)]), "r"(1u << (n1 & 31))
                     : "memory");

    // ---- arrive: one membar to order REDG before the done-count release ----
    __syncthreads();
    __shared__ unsigned s_done;
    if (t == 0) {
        __threadfence();                              // order REDGs (CTA-wide drained by bar)
        s_done = atomicAdd(&g_done[b], 1u);
    }
    __syncthreads();

    if (s_done != SEGS - 1) return;        // not the last CTA of this batch

    // ========== finisher CTA for batch b (wait-free: all others arrived) ====
    __threadfence();                       // acquire side

    unsigned w = __ldcg(&g_mask[b * WORDS + t]);      // one word per thread
    int cnt = __popc(w);

    // Inclusive warp scan of per-word counts
    int inc = cnt;
#pragma unroll
    for (int d = 1; d < 32; d <<= 1) {
        int y = __shfl_up_sync(0xffffffffu, inc, d);
        if (lane >= d) inc += y;
    }

    __shared__ int s_wsum[8];
    if (lane == 31) s_wsum[wid] = inc;
    __syncthreads();

    if (wid == 0) {
        int wv = (lane < 8) ? s_wsum[lane] : 0;
        int winc = wv;
#pragma unroll
        for (int d = 1; d < 8; d <<= 1) {
            int y = __shfl_up_sync(0xffffffffu, winc, d);
            if (lane >= d) winc += y;
        }
        if (lane < 8) s_wsum[lane] = winc - wv;       // exclusive warp base
    }
    __syncthreads();

    int pos = s_wsum[wid] + (inc - cnt);              // exclusive thread base

    // Emit set-bit positions in ascending order (bitmask => sorted for free)
    float* oidx = out + (size_t)PB * PN + (size_t)b * PK;
    while (w) {
        int bit = __ffs(w) - 1;
        w &= w - 1;
        if (pos < PK) oidx[pos] = (float)(t * 32 + bit);
        pos++;
    }

    // ---- reset scratch for the next graph replay ----
    g_mask[b * WORDS + t] = 0u;
    if (t == 0) g_done[b] = 0u;
}

extern "C" void kernel_launch(void* const* d_in, const int* in_sizes, int n_in,
                              void* d_out, int out_size)
{
    const float* one_hot = (const float*)d_in[0];
    const int*   id_ptr  = (const int*)d_in[1];
    float*       out     = (float*)d_out;

    (void)in_sizes; (void)n_in; (void)out_size;

    fused_filter_kernel<<<PB * SEGS, TPB>>>(one_hot, id_ptr, out);
}